// round 1
// baseline (speedup 1.0000x reference)
#include <cuda_runtime.h>
#include <math.h>

// Problem constants
#define L_   4096          // H*W
#define C_   256
#define B_   4
#define NN_  16384         // B*H*W (BN population per channel)

// ---------------- scratch (device globals; no allocation allowed) ----------
__device__ float g_y1[B_*C_*L_];      // conv1 output (pre-BN, bias added)
__device__ float g_y2[B_*C_*L_];      // conv2 output
__device__ float g_pre[B_*C_*L_];     // attention output
__device__ float g_y3[B_*C_*L_];      // conv3 output
__device__ float g_stats[6][C_];      // sum/sumsq for bn1,bn2,bn3
__device__ float g_ab[6][C_];         // a/b affine params for bn1,bn2,bn3

// ---------------- helpers ---------------------------------------------------
__device__ __forceinline__ unsigned long long ffma2(unsigned long long a,
                                                    unsigned long long b,
                                                    unsigned long long c) {
    unsigned long long d;
    asm("fma.rn.f32x2 %0, %1, %2, %3;" : "=l"(d) : "l"(a), "l"(b), "l"(c));
    return d;
}
__device__ __forceinline__ unsigned long long pk2(float a, float b) {
    unsigned long long v;
    asm("mov.b64 %0, {%1,%2};" : "=l"(v) : "f"(a), "f"(b));
    return v;
}
__device__ __forceinline__ float2 upk2(unsigned long long v) {
    float2 f;
    asm("mov.b64 {%0,%1}, %2;" : "=f"(f.x), "=f"(f.y) : "l"(v));
    return f;
}

// ---------------- kernel 0: zero the stats accumulators ---------------------
__global__ void zero_stats_kernel() {
    int i = blockIdx.x * blockDim.x + threadIdx.x;
    if (i < 6 * C_) ((float*)g_stats)[i] = 0.f;
}

// ---------------- GEMM (conv1x1) + column stats ------------------------------
// MODE 0: dual GEMM  x @ w1^T -> g_y1, x @ w2^T -> g_y2, stats rows 0..3
// MODE 1: single     g_pre @ wf^T -> g_y3, stats rows 4..5
// Tile: 128 hw x 64 o, 256 threads, per-thread 4(o) x 8(hw) via f32x2 FMA.
template <int MODE>
__global__ __launch_bounds__(256) void gemm_kernel(
    const float* __restrict__ Xin,
    const float* __restrict__ W1, const float* __restrict__ Bias1,
    const float* __restrict__ W2, const float* __restrict__ Bias2)
{
    const float* X  = (MODE == 1) ? g_pre : Xin;
    float*       Y1 = (MODE == 1) ? g_y3  : g_y1;
    const int sbase = (MODE == 1) ? 4 : 0;

    __shared__ float Xs[16][132];
    __shared__ unsigned long long Wd1[16][68];
    __shared__ unsigned long long Wd2[(MODE == 0) ? 16 : 1][68];
    __shared__ float red[4][64];

    const int tid = threadIdx.x;
    const int tx = tid & 15;        // hw micro-tile (8 floats each)
    const int ty = tid >> 4;        // o micro-tile (4 each)
    const int n0 = blockIdx.x * 128;
    const int b  = n0 >> 12;
    const int hw0 = n0 & 4095;
    const int o0 = blockIdx.y * 64;

    if (tid < 64) { red[0][tid] = 0.f; red[1][tid] = 0.f; red[2][tid] = 0.f; red[3][tid] = 0.f; }

    unsigned long long acc1[4][4];
    unsigned long long acc2[4][4];
#pragma unroll
    for (int i = 0; i < 4; i++)
#pragma unroll
        for (int j = 0; j < 4; j++) { acc1[i][j] = 0ull; acc2[i][j] = 0ull; }

    const int rl = tid & 127;       // hw for X loads
    const int kb = tid >> 7;        // 0/1
    const int kc = tid & 15;        // c for W loads
    const int ob = tid >> 4;        // 0..15

    for (int c0 = 0; c0 < 256; c0 += 16) {
        const float* xp = X + ((size_t)(b * 256 + c0 + kb)) * L_ + hw0 + rl;
#pragma unroll
        for (int kk = 0; kk < 8; kk++)
            Xs[kb + kk * 2][rl] = xp[(size_t)kk * 2 * L_];

        const float* wp1 = W1 + (o0 + ob * 4) * 256 + c0 + kc;
#pragma unroll
        for (int oo = 0; oo < 4; oo++) {
            float w = wp1[oo * 256];
            Wd1[kc][ob * 4 + oo] = pk2(w, w);
        }
        if (MODE == 0) {
            const float* wp2 = W2 + (o0 + ob * 4) * 256 + c0 + kc;
#pragma unroll
            for (int oo = 0; oo < 4; oo++) {
                float w = wp2[oo * 256];
                Wd2[kc][ob * 4 + oo] = pk2(w, w);
            }
        }
        __syncthreads();
#pragma unroll
        for (int k = 0; k < 16; k++) {
            ulonglong2 xa = *(const ulonglong2*)&Xs[k][tx * 8];
            ulonglong2 xb = *(const ulonglong2*)(&Xs[k][tx * 8 + 4]);
#pragma unroll
            for (int i = 0; i < 4; i++) {
                unsigned long long wv = Wd1[k][ty * 4 + i];
                acc1[i][0] = ffma2(wv, xa.x, acc1[i][0]);
                acc1[i][1] = ffma2(wv, xa.y, acc1[i][1]);
                acc1[i][2] = ffma2(wv, xb.x, acc1[i][2]);
                acc1[i][3] = ffma2(wv, xb.y, acc1[i][3]);
                if (MODE == 0) {
                    unsigned long long wv2 = Wd2[k][ty * 4 + i];
                    acc2[i][0] = ffma2(wv2, xa.x, acc2[i][0]);
                    acc2[i][1] = ffma2(wv2, xa.y, acc2[i][1]);
                    acc2[i][2] = ffma2(wv2, xb.x, acc2[i][2]);
                    acc2[i][3] = ffma2(wv2, xb.y, acc2[i][3]);
                }
            }
        }
        __syncthreads();
    }

    // epilogue: bias add, store, per-o partial stats
    const int hwb = hw0 + tx * 8;
#pragma unroll
    for (int i = 0; i < 4; i++) {
        const int ol = ty * 4 + i;
        const int o = o0 + ol;
        {
            float bv = Bias1[o];
            float v[8];
#pragma unroll
            for (int j = 0; j < 4; j++) {
                float2 f = upk2(acc1[i][j]);
                v[2 * j] = f.x + bv; v[2 * j + 1] = f.y + bv;
            }
            float s = 0.f, q = 0.f;
#pragma unroll
            for (int j = 0; j < 8; j++) { s += v[j]; q += v[j] * v[j]; }
            float* yp = Y1 + ((size_t)(b * 256 + o)) * L_ + hwb;
            ((float4*)yp)[0] = make_float4(v[0], v[1], v[2], v[3]);
            ((float4*)yp)[1] = make_float4(v[4], v[5], v[6], v[7]);
            atomicAdd(&red[0][ol], s);
            atomicAdd(&red[1][ol], q);
        }
        if (MODE == 0) {
            float bv = Bias2[o];
            float v[8];
#pragma unroll
            for (int j = 0; j < 4; j++) {
                float2 f = upk2(acc2[i][j]);
                v[2 * j] = f.x + bv; v[2 * j + 1] = f.y + bv;
            }
            float s = 0.f, q = 0.f;
#pragma unroll
            for (int j = 0; j < 8; j++) { s += v[j]; q += v[j] * v[j]; }
            float* yp = g_y2 + ((size_t)(b * 256 + o)) * L_ + hwb;
            ((float4*)yp)[0] = make_float4(v[0], v[1], v[2], v[3]);
            ((float4*)yp)[1] = make_float4(v[4], v[5], v[6], v[7]);
            atomicAdd(&red[2][ol], s);
            atomicAdd(&red[3][ol], q);
        }
    }
    __syncthreads();
    if (tid < 64) {
        atomicAdd(&g_stats[sbase + 0][o0 + tid], red[0][tid]);
        atomicAdd(&g_stats[sbase + 1][o0 + tid], red[1][tid]);
        if (MODE == 0) {
            atomicAdd(&g_stats[2][o0 + tid], red[2][tid]);
            atomicAdd(&g_stats[3][o0 + tid], red[3][tid]);
        }
    }
}

// ---------------- BN affine params from stats --------------------------------
__global__ void bnparam_kernel(int which, const float* __restrict__ g,
                               const float* __restrict__ be) {
    int o = threadIdx.x;
    float mu  = g_stats[2 * which][o] * (1.f / NN_);
    float var = g_stats[2 * which + 1][o] * (1.f / NN_) - mu * mu;
    float a = g[o] * rsqrtf(var + 1e-5f);
    g_ab[2 * which][o] = a;
    g_ab[2 * which + 1][o] = be[o] - mu * a;
}

// ---------------- attention (flat-domain, faithful to the reshape bug) ------
// Per (b,c): flat domain of 9L values. Flat n -> unfold position P=n/L, l=n%L.
// Softmax groups = consecutive 9-chunks of flat index. Output l'' = m % L,
// summing the 9 slabs m = p*L + l''.
__global__ __launch_bounds__(512) void attn_kernel(const float* __restrict__ X) {
    __shared__ float sku[528], squ[528], swt[528];
    const int tid = threadIdx.x;
    const int t0 = blockIdx.x * 512;
    const int c = blockIdx.y;
    const int b = blockIdx.z;

    const float a1 = g_ab[0][c], b1 = g_ab[1][c];
    const float a2 = g_ab[2][c], b2 = g_ab[3][c];
    const float* Y1 = g_y1 + ((size_t)(b * 256 + c)) * L_;
    const float* Y2 = g_y2 + ((size_t)(b * 256 + c)) * L_;
    const float* Xc = X + ((size_t)(b * 256 + c)) * L_;

    float acc = 0.f;
    for (int p = 0; p < 9; p++) {
        const int m0 = p * L_ + t0;
        const int g0 = m0 / 9;
        const int g1 = (m0 + 511) / 9;
        const int nG = g1 - g0 + 1;
        const int span = nG * 9;
        const int nbase = g0 * 9;

        // stage ku/qu for the group-aligned flat span
        for (int i = tid; i < span; i += 512) {
            int n = nbase + i;
            int P = n >> 12;
            int l = n & 4095;
            int pi = P / 3;
            int pj = P - pi * 3;
            int hh = (l >> 6) + pi - 1;
            int ww = (l & 63) + pj - 1;
            float kv = 0.f, qv = 0.f;
            if ((unsigned)hh < 64u && (unsigned)ww < 64u) {
                int off = (hh << 6) + ww;
                kv = fmaxf(fmaf(a1, Y1[off], b1), 0.f);
                qv = fmaxf(fmaf(a2, Y2[off], b2), 0.f);
            }
            sku[i] = kv;
            squ[i] = qv;
        }
        __syncthreads();

        // cooperative softmax, one thread per group of 9
        if (tid < nG) {
            int o = tid * 9;
            float kcv = sku[o + 4], qcv = squ[o + 4];
            float lg[9];
            float mx = -1e30f;
#pragma unroll
            for (int j = 0; j < 9; j++) {
                lg[j] = sku[o + j] * qcv + kcv * squ[o + j];
                mx = fmaxf(mx, lg[j]);
            }
            float s = 0.f;
#pragma unroll
            for (int j = 0; j < 9; j++) {
                float e = __expf(lg[j] - mx);
                lg[j] = e;
                s += e;
            }
            float inv = 1.f / s;
#pragma unroll
            for (int j = 0; j < 9; j++) swt[o + j] = lg[j] * inv;
        }
        __syncthreads();

        // consume: weight * unfold(x) at (P=p, l = t0+tid)
        {
            int l = t0 + tid;
            int pi = p / 3;
            int pj = p - pi * 3;
            int hh = (l >> 6) + pi - 1;
            int ww = (l & 63) + pj - 1;
            float xv = 0.f;
            if ((unsigned)hh < 64u && (unsigned)ww < 64u) xv = Xc[(hh << 6) + ww];
            acc += swt[m0 - nbase + tid] * xv;
        }
        __syncthreads();
    }
    g_pre[((size_t)(b * 256 + c)) * L_ + t0 + tid] = acc;
}

// ---------------- final: out = relu(a3*y3 + b3) ------------------------------
__global__ void final_kernel(float* __restrict__ out) {
    int i = blockIdx.x * blockDim.x + threadIdx.x;   // float4 index
    float4 v = ((const float4*)g_y3)[i];
    int o = (i >> 10) & 255;                          // 4096 floats = 1024 f4 per channel
    float a = g_ab[4][o], bb = g_ab[5][o];
    v.x = fmaxf(fmaf(a, v.x, bb), 0.f);
    v.y = fmaxf(fmaf(a, v.y, bb), 0.f);
    v.z = fmaxf(fmaf(a, v.z, bb), 0.f);
    v.w = fmaxf(fmaf(a, v.w, bb), 0.f);
    ((float4*)out)[i] = v;
}

// ---------------- launcher ---------------------------------------------------
extern "C" void kernel_launch(void* const* d_in, const int* in_sizes, int n_in,
                              void* d_out, int out_size) {
    const float* x   = (const float*)d_in[0];
    const float* w1  = (const float*)d_in[1];
    const float* b1  = (const float*)d_in[2];
    const float* g1  = (const float*)d_in[3];
    const float* be1 = (const float*)d_in[4];
    const float* w2  = (const float*)d_in[5];
    const float* b2  = (const float*)d_in[6];
    const float* g2  = (const float*)d_in[7];
    const float* be2 = (const float*)d_in[8];
    const float* wf  = (const float*)d_in[9];
    const float* bf  = (const float*)d_in[10];
    const float* gf  = (const float*)d_in[11];
    const float* bef = (const float*)d_in[12];
    float* out = (float*)d_out;

    zero_stats_kernel<<<3, 512>>>();
    gemm_kernel<0><<<dim3(128, 4), 256>>>(x, w1, b1, w2, b2);
    bnparam_kernel<<<1, 256>>>(0, g1, be1);
    bnparam_kernel<<<1, 256>>>(1, g2, be2);
    attn_kernel<<<dim3(8, 256, 4), 512>>>(x);
    gemm_kernel<1><<<dim3(128, 4), 256>>>(nullptr, wf, bf, nullptr, nullptr);
    bnparam_kernel<<<1, 256>>>(2, gf, bef);
    final_kernel<<<4096, 256>>>(out);
}

// round 2
// speedup vs baseline: 1.3615x; 1.3615x over previous
#include <cuda_runtime.h>
#include <math.h>

#define L_   4096
#define C_   256
#define B_   4
#define NN_  16384

// ---------------- scratch ----------------------------------------------------
__device__ float g_y1[B_*C_*L_];
__device__ float g_y2[B_*C_*L_];
__device__ float g_pre[B_*C_*L_];
__device__ float g_y3[B_*C_*L_];
__device__ float g_stats[6][C_];
__device__ float g_ab[6][C_];

// ---------------- helpers ----------------------------------------------------
__device__ __forceinline__ unsigned long long ffma2(unsigned long long a,
                                                    unsigned long long b,
                                                    unsigned long long c) {
    unsigned long long d;
    asm("fma.rn.f32x2 %0, %1, %2, %3;" : "=l"(d) : "l"(a), "l"(b), "l"(c));
    return d;
}
__device__ __forceinline__ unsigned long long pk2(float a, float b) {
    unsigned long long v;
    asm("mov.b64 %0, {%1,%2};" : "=l"(v) : "f"(a), "f"(b));
    return v;
}
__device__ __forceinline__ float2 upk2(unsigned long long v) {
    float2 f;
    asm("mov.b64 {%0,%1}, %2;" : "=f"(f.x), "=f"(f.y) : "l"(v));
    return f;
}

// ---------------- zero stats --------------------------------------------------
__global__ void zero_stats_kernel() {
    int i = blockIdx.x * blockDim.x + threadIdx.x;
    if (i < 6 * C_) ((float*)g_stats)[i] = 0.f;
}

// ---------------- GEMM: 256hw x 64o tile, conflict-free smem ------------------
// MODE 0: dual GEMM x@w1^T -> g_y1, x@w2^T -> g_y2 (+stats rows 0..3)
// MODE 1: g_pre@wf^T -> g_y3 (+stats rows 4..5)
// 256 threads; per-thread 4(o) x 16(hw), hw mapped as q*64 + tx*4 (q=0..3).
template <int MODE>
__global__ __launch_bounds__(256) void gemm_kernel(
    const float* __restrict__ Xin,
    const float* __restrict__ W1, const float* __restrict__ Bias1,
    const float* __restrict__ W2, const float* __restrict__ Bias2)
{
    const float* X  = (MODE == 1) ? g_pre : Xin;
    float*       Y1 = (MODE == 1) ? g_y3  : g_y1;
    const int sbase = (MODE == 1) ? 4 : 0;

    __shared__ float Xs[16][260];
    __shared__ unsigned long long Wd1[16][68];
    __shared__ unsigned long long Wd2[(MODE == 0) ? 16 : 1][68];
    __shared__ float red[4][64];

    const int tid = threadIdx.x;
    const int tx = tid & 15;
    const int ty = tid >> 4;
    const int n0 = blockIdx.x * 256;
    const int b  = n0 >> 12;
    const int hw0 = n0 & 4095;
    const int o0 = blockIdx.y * 64;

    if (tid < 64) { red[0][tid] = 0.f; red[1][tid] = 0.f; red[2][tid] = 0.f; red[3][tid] = 0.f; }

    unsigned long long acc1[4][8];
    unsigned long long acc2[4][8];
#pragma unroll
    for (int i = 0; i < 4; i++)
#pragma unroll
        for (int j = 0; j < 8; j++) { acc1[i][j] = 0ull; acc2[i][j] = 0ull; }

    const int kc = tid & 15;
    const int ob = tid >> 4;

    for (int c0 = 0; c0 < 256; c0 += 16) {
        // stage X: 16 c-rows x 256 hw, thread tid owns column tid
        const float* xp = X + ((size_t)(b * 256 + c0)) * L_ + hw0 + tid;
#pragma unroll
        for (int cc = 0; cc < 16; cc++)
            Xs[cc][tid] = xp[(size_t)cc * L_];

        // stage W (duplicated halves for f32x2)
        const float* wp1 = W1 + (o0 + ob * 4) * 256 + c0 + kc;
#pragma unroll
        for (int oo = 0; oo < 4; oo++) {
            float w = wp1[oo * 256];
            Wd1[kc][ob * 4 + oo] = pk2(w, w);
        }
        if (MODE == 0) {
            const float* wp2 = W2 + (o0 + ob * 4) * 256 + c0 + kc;
#pragma unroll
            for (int oo = 0; oo < 4; oo++) {
                float w = wp2[oo * 256];
                Wd2[kc][ob * 4 + oo] = pk2(w, w);
            }
        }
        __syncthreads();
#pragma unroll
        for (int k = 0; k < 16; k++) {
            ulonglong2 xq[4];
#pragma unroll
            for (int q = 0; q < 4; q++)
                xq[q] = *(const ulonglong2*)&Xs[k][q * 64 + tx * 4];
#pragma unroll
            for (int i = 0; i < 4; i++) {
                unsigned long long wv = Wd1[k][ty * 4 + i];
#pragma unroll
                for (int q = 0; q < 4; q++) {
                    acc1[i][2 * q]     = ffma2(wv, xq[q].x, acc1[i][2 * q]);
                    acc1[i][2 * q + 1] = ffma2(wv, xq[q].y, acc1[i][2 * q + 1]);
                }
                if (MODE == 0) {
                    unsigned long long wv2 = Wd2[k][ty * 4 + i];
#pragma unroll
                    for (int q = 0; q < 4; q++) {
                        acc2[i][2 * q]     = ffma2(wv2, xq[q].x, acc2[i][2 * q]);
                        acc2[i][2 * q + 1] = ffma2(wv2, xq[q].y, acc2[i][2 * q + 1]);
                    }
                }
            }
        }
        __syncthreads();
    }

    // epilogue
#pragma unroll
    for (int i = 0; i < 4; i++) {
        const int ol = ty * 4 + i;
        const int o = o0 + ol;
        {
            float bv = Bias1[o];
            float s = 0.f, qs = 0.f;
            float* yp = Y1 + ((size_t)(b * 256 + o)) * L_ + hw0 + tx * 4;
#pragma unroll
            for (int q = 0; q < 4; q++) {
                float2 fa = upk2(acc1[i][2 * q]);
                float2 fb = upk2(acc1[i][2 * q + 1]);
                float4 v = make_float4(fa.x + bv, fa.y + bv, fb.x + bv, fb.y + bv);
                s += v.x + v.y + v.z + v.w;
                qs += v.x * v.x + v.y * v.y + v.z * v.z + v.w * v.w;
                *(float4*)(yp + q * 64) = v;
            }
            atomicAdd(&red[0][ol], s);
            atomicAdd(&red[1][ol], qs);
        }
        if (MODE == 0) {
            float bv = Bias2[o];
            float s = 0.f, qs = 0.f;
            float* yp = g_y2 + ((size_t)(b * 256 + o)) * L_ + hw0 + tx * 4;
#pragma unroll
            for (int q = 0; q < 4; q++) {
                float2 fa = upk2(acc2[i][2 * q]);
                float2 fb = upk2(acc2[i][2 * q + 1]);
                float4 v = make_float4(fa.x + bv, fa.y + bv, fb.x + bv, fb.y + bv);
                s += v.x + v.y + v.z + v.w;
                qs += v.x * v.x + v.y * v.y + v.z * v.z + v.w * v.w;
                *(float4*)(yp + q * 64) = v;
            }
            atomicAdd(&red[2][ol], s);
            atomicAdd(&red[3][ol], qs);
        }
    }
    __syncthreads();
    if (tid < 64) {
        atomicAdd(&g_stats[sbase + 0][o0 + tid], red[0][tid]);
        atomicAdd(&g_stats[sbase + 1][o0 + tid], red[1][tid]);
        if (MODE == 0) {
            atomicAdd(&g_stats[2][o0 + tid], red[2][tid]);
            atomicAdd(&g_stats[3][o0 + tid], red[3][tid]);
        }
    }
}

// ---------------- BN affine params -------------------------------------------
__global__ void bnparam12_kernel(const float* __restrict__ g1, const float* __restrict__ be1,
                                 const float* __restrict__ g2, const float* __restrict__ be2) {
    int o = threadIdx.x & 255;
    int which = threadIdx.x >> 8;
    const float* g  = which ? g2 : g1;
    const float* be = which ? be2 : be1;
    float mu  = g_stats[2 * which][o] * (1.f / NN_);
    float var = g_stats[2 * which + 1][o] * (1.f / NN_) - mu * mu;
    float a = g[o] * rsqrtf(var + 1e-5f);
    g_ab[2 * which][o] = a;
    g_ab[2 * which + 1][o] = be[o] - mu * a;
}
__global__ void bnparam3_kernel(const float* __restrict__ g, const float* __restrict__ be) {
    int o = threadIdx.x;
    float mu  = g_stats[4][o] * (1.f / NN_);
    float var = g_stats[5][o] * (1.f / NN_) - mu * mu;
    float a = g[o] * rsqrtf(var + 1e-5f);
    g_ab[4][o] = a;
    g_ab[5][o] = be[o] - mu * a;
}

// ---------------- attention: 2-sync version -----------------------------------
// Per block: 512 outputs (l'' = t0..t0+511) of one (b,c).
// Stage all 9 slabs' group-aligned flat spans, softmax all groups in parallel
// (in-place into sku), then one consume pass.
__global__ __launch_bounds__(512) void attn_kernel(const float* __restrict__ X) {
    __shared__ float sku[9][528];
    __shared__ float squ[9][528];
    const int tid = threadIdx.x;
    const int t0 = blockIdx.x * 512;
    const int c = blockIdx.y;
    const int b = blockIdx.z;

    const float a1 = g_ab[0][c], b1 = g_ab[1][c];
    const float a2 = g_ab[2][c], b2 = g_ab[3][c];
    const float* Y1 = g_y1 + ((size_t)(b * 256 + c)) * L_;
    const float* Y2 = g_y2 + ((size_t)(b * 256 + c)) * L_;
    const float* Xc = X + ((size_t)(b * 256 + c)) * L_;

    int nbase[9];
#pragma unroll
    for (int s = 0; s < 9; s++) nbase[s] = ((s * 4096 + t0) / 9) * 9;

    // Phase 1: stage bn-relu'd ku/qu for all 9 slabs
#pragma unroll
    for (int s = 0; s < 9; s++) {
        const int span = ((s * 4096 + t0 + 511) / 9 + 1) * 9 - nbase[s];
        for (int i = tid; i < span; i += 512) {
            int n = nbase[s] + i;
            int P = n >> 12;
            int l = n & 4095;
            int pi = P / 3;
            int pj = P - pi * 3;
            int hh = (l >> 6) + pi - 1;
            int ww = (l & 63) + pj - 1;
            float kv = 0.f, qv = 0.f;
            if ((unsigned)hh < 64u && (unsigned)ww < 64u) {
                int off = (hh << 6) + ww;
                kv = fmaxf(fmaf(a1, Y1[off], b1), 0.f);
                qv = fmaxf(fmaf(a2, Y2[off], b2), 0.f);
            }
            sku[s][i] = kv;
            squ[s][i] = qv;
        }
    }
    __syncthreads();

    // Phase 2: softmax, one group per thread, weights written in place over sku
    for (int t = tid; t < 9 * 59; t += 512) {
        int s = t / 59;
        int j = t - s * 59;
        int nG = (s * 4096 + t0 + 511) / 9 - nbase[s] / 9 + 1;
        if (j < nG) {
            float* kp = &sku[s][j * 9];
            float* qp = &squ[s][j * 9];
            float kc4 = kp[4], qc4 = qp[4];
            float lg[9];
            float mx = -1e30f;
#pragma unroll
            for (int jj = 0; jj < 9; jj++) {
                lg[jj] = kp[jj] * qc4 + kc4 * qp[jj];
                mx = fmaxf(mx, lg[jj]);
            }
            float ssum = 0.f;
#pragma unroll
            for (int jj = 0; jj < 9; jj++) {
                float e = __expf(lg[jj] - mx);
                lg[jj] = e;
                ssum += e;
            }
            float inv = 1.f / ssum;
#pragma unroll
            for (int jj = 0; jj < 9; jj++) kp[jj] = lg[jj] * inv;
        }
    }
    __syncthreads();

    // Phase 3: consume — one output per thread
    const int l = t0 + tid;
    const int r = l >> 6;
    const int col = l & 63;
    float acc = 0.f;
#pragma unroll
    for (int p = 0; p < 9; p++) {
        int pi = p / 3;
        int pj = p - pi * 3;
        int hh = r + pi - 1;
        int ww = col + pj - 1;
        float xv = 0.f;
        if ((unsigned)hh < 64u && (unsigned)ww < 64u) xv = Xc[(hh << 6) + ww];
        acc += sku[p][p * 4096 + t0 - nbase[p] + tid] * xv;
    }
    g_pre[((size_t)(b * 256 + c)) * L_ + l] = acc;
}

// ---------------- final BN+ReLU ----------------------------------------------
__global__ void final_kernel(float* __restrict__ out) {
    int i = blockIdx.x * blockDim.x + threadIdx.x;
    float4 v = ((const float4*)g_y3)[i];
    int o = (i >> 10) & 255;
    float a = g_ab[4][o], bb = g_ab[5][o];
    v.x = fmaxf(fmaf(a, v.x, bb), 0.f);
    v.y = fmaxf(fmaf(a, v.y, bb), 0.f);
    v.z = fmaxf(fmaf(a, v.z, bb), 0.f);
    v.w = fmaxf(fmaf(a, v.w, bb), 0.f);
    ((float4*)out)[i] = v;
}

// ---------------- launcher ----------------------------------------------------
extern "C" void kernel_launch(void* const* d_in, const int* in_sizes, int n_in,
                              void* d_out, int out_size) {
    const float* x   = (const float*)d_in[0];
    const float* w1  = (const float*)d_in[1];
    const float* b1  = (const float*)d_in[2];
    const float* g1  = (const float*)d_in[3];
    const float* be1 = (const float*)d_in[4];
    const float* w2  = (const float*)d_in[5];
    const float* b2  = (const float*)d_in[6];
    const float* g2  = (const float*)d_in[7];
    const float* be2 = (const float*)d_in[8];
    const float* wf  = (const float*)d_in[9];
    const float* bf  = (const float*)d_in[10];
    const float* gf  = (const float*)d_in[11];
    const float* bef = (const float*)d_in[12];
    float* out = (float*)d_out;

    zero_stats_kernel<<<3, 512>>>();
    gemm_kernel<0><<<dim3(64, 4), 256>>>(x, w1, b1, w2, b2);
    bnparam12_kernel<<<1, 512>>>(g1, be1, g2, be2);
    attn_kernel<<<dim3(8, 256, 4), 512>>>(x);
    gemm_kernel<1><<<dim3(64, 4), 256>>>(nullptr, wf, bf, nullptr, nullptr);
    bnparam3_kernel<<<1, 256>>>(gf, bef);
    final_kernel<<<4096, 256>>>(out);
}

// round 3
// speedup vs baseline: 1.4789x; 1.0862x over previous
#include <cuda_runtime.h>
#include <math.h>

#define L_   4096
#define C_   256
#define B_   4
#define NN_  16384

// ---------------- scratch ----------------------------------------------------
__device__ float g_y1[B_*C_*L_];
__device__ float g_y2[B_*C_*L_];
__device__ float g_pre[B_*C_*L_];
__device__ float g_y3[B_*C_*L_];
__device__ float g_stats[6][C_];
__device__ float g_ab[6][C_];

// ---------------- helpers ----------------------------------------------------
__device__ __forceinline__ unsigned long long ffma2(unsigned long long a,
                                                    unsigned long long b,
                                                    unsigned long long c) {
    unsigned long long d;
    asm("fma.rn.f32x2 %0, %1, %2, %3;" : "=l"(d) : "l"(a), "l"(b), "l"(c));
    return d;
}
__device__ __forceinline__ unsigned long long pk2(float a, float b) {
    unsigned long long v;
    asm("mov.b64 %0, {%1,%2};" : "=l"(v) : "f"(a), "f"(b));
    return v;
}
__device__ __forceinline__ float2 upk2(unsigned long long v) {
    float2 f;
    asm("mov.b64 {%0,%1}, %2;" : "=f"(f.x), "=f"(f.y) : "l"(v));
    return f;
}

// ---------------- zero stats --------------------------------------------------
__global__ void zero_stats_kernel() {
    int i = blockIdx.x * blockDim.x + threadIdx.x;
    if (i < 6 * C_) ((float*)g_stats)[i] = 0.f;
}

// ---------------- GEMM: 256hw x 64o tile, one weight matrix per block --------
// MODE 0: z=0 -> x@w1^T -> g_y1 (stats 0,1); z=1 -> x@w2^T -> g_y2 (stats 2,3)
// MODE 1: g_pre@wf^T -> g_y3 (stats 4,5)
template <int MODE>
__global__ __launch_bounds__(256) void gemm_kernel(
    const float* __restrict__ Xin,
    const float* __restrict__ W1, const float* __restrict__ Bias1,
    const float* __restrict__ W2, const float* __restrict__ Bias2)
{
    const int z = blockIdx.z;
    const float* X    = (MODE == 1) ? g_pre : Xin;
    const float* W    = (MODE == 0 && z == 1) ? W2 : W1;
    const float* Bias = (MODE == 0 && z == 1) ? Bias2 : Bias1;
    float*       Y    = (MODE == 1) ? g_y3 : (z ? g_y2 : g_y1);
    const int sbase   = (MODE == 1) ? 4 : 2 * z;

    __shared__ float Xs[16][260];
    __shared__ unsigned long long Wd[16][68];
    __shared__ float red[2][64];

    const int tid = threadIdx.x;
    const int tx = tid & 15;
    const int ty = tid >> 4;
    const int n0 = blockIdx.x * 256;
    const int b  = n0 >> 12;
    const int hw0 = n0 & 4095;
    const int o0 = blockIdx.y * 64;

    if (tid < 64) { red[0][tid] = 0.f; red[1][tid] = 0.f; }

    unsigned long long acc[4][8];
#pragma unroll
    for (int i = 0; i < 4; i++)
#pragma unroll
        for (int j = 0; j < 8; j++) acc[i][j] = 0ull;

    const int kc = tid & 15;
    const int ob = tid >> 4;

    for (int c0 = 0; c0 < 256; c0 += 16) {
        const float* xp = X + ((size_t)(b * 256 + c0)) * L_ + hw0 + tid;
#pragma unroll
        for (int cc = 0; cc < 16; cc++)
            Xs[cc][tid] = xp[(size_t)cc * L_];

        const float* wp = W + (o0 + ob * 4) * 256 + c0 + kc;
#pragma unroll
        for (int oo = 0; oo < 4; oo++) {
            float w = wp[oo * 256];
            Wd[kc][ob * 4 + oo] = pk2(w, w);
        }
        __syncthreads();
#pragma unroll
        for (int k = 0; k < 16; k++) {
            ulonglong2 xq[4];
#pragma unroll
            for (int q = 0; q < 4; q++)
                xq[q] = *(const ulonglong2*)&Xs[k][q * 64 + tx * 4];
#pragma unroll
            for (int i = 0; i < 4; i++) {
                unsigned long long wv = Wd[k][ty * 4 + i];
#pragma unroll
                for (int q = 0; q < 4; q++) {
                    acc[i][2 * q]     = ffma2(wv, xq[q].x, acc[i][2 * q]);
                    acc[i][2 * q + 1] = ffma2(wv, xq[q].y, acc[i][2 * q + 1]);
                }
            }
        }
        __syncthreads();
    }

#pragma unroll
    for (int i = 0; i < 4; i++) {
        const int ol = ty * 4 + i;
        const int o = o0 + ol;
        float bv = Bias[o];
        float s = 0.f, qs = 0.f;
        float* yp = Y + ((size_t)(b * 256 + o)) * L_ + hw0 + tx * 4;
#pragma unroll
        for (int q = 0; q < 4; q++) {
            float2 fa = upk2(acc[i][2 * q]);
            float2 fb = upk2(acc[i][2 * q + 1]);
            float4 v = make_float4(fa.x + bv, fa.y + bv, fb.x + bv, fb.y + bv);
            s += v.x + v.y + v.z + v.w;
            qs += v.x * v.x + v.y * v.y + v.z * v.z + v.w * v.w;
            *(float4*)(yp + q * 64) = v;
        }
        atomicAdd(&red[0][ol], s);
        atomicAdd(&red[1][ol], qs);
    }
    __syncthreads();
    if (tid < 64) {
        atomicAdd(&g_stats[sbase + 0][o0 + tid], red[0][tid]);
        atomicAdd(&g_stats[sbase + 1][o0 + tid], red[1][tid]);
    }
}

// ---------------- BN affine params -------------------------------------------
__global__ void bnparam12_kernel(const float* __restrict__ g1, const float* __restrict__ be1,
                                 const float* __restrict__ g2, const float* __restrict__ be2) {
    int o = threadIdx.x & 255;
    int which = threadIdx.x >> 8;
    const float* g  = which ? g2 : g1;
    const float* be = which ? be2 : be1;
    float mu  = g_stats[2 * which][o] * (1.f / NN_);
    float var = g_stats[2 * which + 1][o] * (1.f / NN_) - mu * mu;
    float a = g[o] * rsqrtf(var + 1e-5f);
    g_ab[2 * which][o] = a;
    g_ab[2 * which + 1][o] = be[o] - mu * a;
}
__global__ void bnparam3_kernel(const float* __restrict__ g, const float* __restrict__ be) {
    int o = threadIdx.x;
    float mu  = g_stats[4][o] * (1.f / NN_);
    float var = g_stats[5][o] * (1.f / NN_) - mu * mu;
    float a = g[o] * rsqrtf(var + 1e-5f);
    g_ab[4][o] = a;
    g_ab[5][o] = be[o] - mu * a;
}

// ---------------- attention: spatial-halo staging ----------------------------
// Block: 512 outputs l = t0..t0+511 of one (b,c). Stage tri1/tri2/x as halo'd
// 12x66 spatial tiles (rows r0-2..r0+9, cols -1..64, zero outside image).
// Phase 2 evaluates group members via the staged tiles (rare P-wrap members
// fall back to global). Phase 3 consumes x from smem.
__global__ __launch_bounds__(512) void attn_kernel(const float* __restrict__ X) {
    __shared__ float st1[12 * 67];
    __shared__ float st2[12 * 67];
    __shared__ float sx [12 * 67];
    __shared__ float sw [9 * 528];

    const int tid = threadIdx.x;
    const int t0 = blockIdx.x * 512;
    const int r0 = t0 >> 6;
    const int c = blockIdx.y;
    const int b = blockIdx.z;

    const float a1 = g_ab[0][c], b1 = g_ab[1][c];
    const float a2 = g_ab[2][c], b2 = g_ab[3][c];
    const float* Y1 = g_y1 + ((size_t)(b * 256 + c)) * L_;
    const float* Y2 = g_y2 + ((size_t)(b * 256 + c)) * L_;
    const float* Xc = X + ((size_t)(b * 256 + c)) * L_;

    // Phase 1: stage halo'd spatial tiles
    for (int i = tid; i < 12 * 66; i += 512) {
        int ri = i / 66;
        int wi = i - ri * 66;
        int gr = r0 - 2 + ri;
        int gc = wi - 1;
        float v1 = 0.f, v2 = 0.f, vx = 0.f;
        if ((unsigned)gr < 64u && (unsigned)gc < 64u) {
            int off = (gr << 6) + gc;
            v1 = fmaxf(fmaf(a1, Y1[off], b1), 0.f);
            v2 = fmaxf(fmaf(a2, Y2[off], b2), 0.f);
            vx = Xc[off];
        }
        st1[ri * 67 + wi] = v1;
        st2[ri * 67 + wi] = v2;
        sx [ri * 67 + wi] = vx;
    }
    __syncthreads();

    // Phase 2: per-group softmax (one group per thread-iteration)
    for (int t = tid; t < 9 * 58; t += 512) {
        int s = t / 58;
        int j = t - s * 58;
        int m0 = s * 4096 + t0;
        int gb = m0 / 9;
        int nG = (m0 + 511) / 9 - gb + 1;
        if (j < nG) {
            int n0 = gb * 9 + j * 9;
            float kv[9], qv[9];
#pragma unroll
            for (int jj = 0; jj < 9; jj++) {
                int n = n0 + jj;
                int P = n >> 12;
                int l = n & 4095;
                int pi = P / 3;
                int pj = P - pi * 3;
                int hh = (l >> 6) + pi - 1;
                int ww = (l & 63) + pj - 1;
                int ri = hh - r0 + 2;
                int wi = ww + 1;
                float k_, q_;
                if ((unsigned)ri < 12u && (unsigned)wi < 66u) {
                    k_ = st1[ri * 67 + wi];
                    q_ = st2[ri * 67 + wi];
                } else if ((unsigned)hh < 64u && (unsigned)ww < 64u) {
                    int off = (hh << 6) + ww;
                    k_ = fmaxf(fmaf(a1, Y1[off], b1), 0.f);
                    q_ = fmaxf(fmaf(a2, Y2[off], b2), 0.f);
                } else { k_ = 0.f; q_ = 0.f; }
                kv[jj] = k_;
                qv[jj] = q_;
            }
            float kc4 = kv[4], qc4 = qv[4];
            float lg[9];
            float mx = -1e30f;
#pragma unroll
            for (int jj = 0; jj < 9; jj++) {
                lg[jj] = kv[jj] * qc4 + kc4 * qv[jj];
                mx = fmaxf(mx, lg[jj]);
            }
            float ssum = 0.f;
#pragma unroll
            for (int jj = 0; jj < 9; jj++) {
                float e = __expf(lg[jj] - mx);
                lg[jj] = e;
                ssum += e;
            }
            float inv = 1.f / ssum;
            float* wp = &sw[s * 528 + j * 9];
#pragma unroll
            for (int jj = 0; jj < 9; jj++) wp[jj] = lg[jj] * inv;
        }
    }
    __syncthreads();

    // Phase 3: consume — one output per thread
    const int tr = tid >> 6;
    const int tc = tid & 63;
    float acc = 0.f;
#pragma unroll
    for (int p = 0; p < 9; p++) {
        int pi = p / 3;
        int pj = p - pi * 3;
        int off = (p * 4096 + t0) % 9;              // compile-time-ish per p
        float w = sw[p * 528 + off + tid];
        float xv = sx[(tr + pi + 1) * 67 + tc + pj];
        acc += w * xv;
    }
    g_pre[((size_t)(b * 256 + c)) * L_ + t0 + tid] = acc;
}

// ---------------- final BN+ReLU ----------------------------------------------
__global__ void final_kernel(float* __restrict__ out) {
    int i = blockIdx.x * blockDim.x + threadIdx.x;
    float4 v = ((const float4*)g_y3)[i];
    int o = (i >> 10) & 255;
    float a = g_ab[4][o], bb = g_ab[5][o];
    v.x = fmaxf(fmaf(a, v.x, bb), 0.f);
    v.y = fmaxf(fmaf(a, v.y, bb), 0.f);
    v.z = fmaxf(fmaf(a, v.z, bb), 0.f);
    v.w = fmaxf(fmaf(a, v.w, bb), 0.f);
    ((float4*)out)[i] = v;
}

// ---------------- launcher ----------------------------------------------------
extern "C" void kernel_launch(void* const* d_in, const int* in_sizes, int n_in,
                              void* d_out, int out_size) {
    const float* x   = (const float*)d_in[0];
    const float* w1  = (const float*)d_in[1];
    const float* b1  = (const float*)d_in[2];
    const float* g1  = (const float*)d_in[3];
    const float* be1 = (const float*)d_in[4];
    const float* w2  = (const float*)d_in[5];
    const float* b2  = (const float*)d_in[6];
    const float* g2  = (const float*)d_in[7];
    const float* be2 = (const float*)d_in[8];
    const float* wf  = (const float*)d_in[9];
    const float* bf  = (const float*)d_in[10];
    const float* gf  = (const float*)d_in[11];
    const float* bef = (const float*)d_in[12];
    float* out = (float*)d_out;

    zero_stats_kernel<<<3, 512>>>();
    gemm_kernel<0><<<dim3(64, 4, 2), 256>>>(x, w1, b1, w2, b2);
    bnparam12_kernel<<<1, 512>>>(g1, be1, g2, be2);
    attn_kernel<<<dim3(8, 256, 4), 512>>>(x);
    gemm_kernel<1><<<dim3(64, 4, 1), 256>>>(nullptr, wf, bf, nullptr, nullptr);
    bnparam3_kernel<<<1, 256>>>(gf, bef);
    final_kernel<<<4096, 256>>>(out);
}